// round 15
// baseline (speedup 1.0000x reference)
#include <cuda_runtime.h>
#include <cstdint>

#define EDIM  64
#define KC    1024
#define NMAX  131072
#define MARGIN 3.2e-4f

// ---------------- device scratch ----------------
__device__ __align__(16) uint2 g_Bfrag[16384];  // [c][s][lane][slot16] bf16(-2cb) frags
__device__ float  g_ee[KC];
__device__ int    g_codes[NMAX];
__device__ unsigned long long g_pairs[NMAX];    // (row<<20)|(i1<<10)|i2
__device__ int    g_full_rows[NMAX];
__device__ unsigned long long g_amb_key[NMAX];
__device__ int    g_seg_cnt[NMAX];
__device__ int    g_n_pair, g_n_full, g_done;
__device__ double g_loss_sum;

// ---------------- helpers ----------------
__device__ __forceinline__ uint32_t smem_to_u32(const void* p) {
    uint32_t a;
    asm("{ .reg .u64 t; cvta.to.shared.u64 t, %1; cvt.u32.u64 %0, t; }" : "=r"(a) : "l"(p));
    return a;
}
__device__ __forceinline__ uint32_t packbf(float lo, float hi) {
    uint32_t r;
    asm("cvt.rn.bf16x2.f32 %0, %1, %2;" : "=r"(r) : "f"(hi), "f"(lo));
    return r;
}
__device__ __forceinline__ void mma_bf16(float* c, const uint32_t* a, uint32_t b0, uint32_t b1) {
    asm volatile("mma.sync.aligned.m16n8k16.row.col.f32.bf16.bf16.f32 "
                 "{%0,%1,%2,%3},{%4,%5,%6,%7},{%8,%9},{%0,%1,%2,%3};"
                 : "+f"(c[0]), "+f"(c[1]), "+f"(c[2]), "+f"(c[3])
                 : "r"(a[0]), "r"(a[1]), "r"(a[2]), "r"(a[3]), "r"(b0), "r"(b1));
}
__device__ __forceinline__ void ldmA(uint32_t* r, uint32_t addr) {
    asm volatile("ldmatrix.sync.aligned.m8n8.x4.shared.b16 {%0,%1,%2,%3}, [%4];"
                 : "=r"(r[0]), "=r"(r[1]), "=r"(r[2]), "=r"(r[3]) : "r"(addr));
}
__device__ __forceinline__ unsigned long long addf2(unsigned long long a, unsigned long long b) {
    unsigned long long r;
    asm("add.rn.f32x2 %0, %1, %2;" : "=l"(r) : "l"(a), "l"(b));
    return r;
}
__device__ __forceinline__ unsigned long long fmaf2(unsigned long long a, unsigned long long b,
                                                    unsigned long long c) {
    unsigned long long r;
    asm("fma.rn.f32x2 %0, %1, %2, %3;" : "=l"(r) : "l"(a), "l"(b), "l"(c));
    return r;
}
#define CP_COMMIT() asm volatile("cp.async.commit_group;" ::: "memory")
#define CP_WAIT0()  asm volatile("cp.async.wait_group 0;" ::: "memory")

__device__ __forceinline__ float ref_xx(const float* xv) {
    float xx = 0.f;
    #pragma unroll
    for (int k = 0; k < EDIM; ++k) xx = __fadd_rn(xx, __fmul_rn(xv[k], xv[k]));
    return xx;
}
__device__ __forceinline__ float ref_dist(const float* xv, const float* e, float xx, float ee) {
    float a = 0.f;
    #pragma unroll
    for (int k = 0; k < EDIM; ++k) a = __fmaf_rn(xv[k], e[k], a);
    return __fadd_rn(__fadd_rn(xx, __fmul_rn(-2.f, a)), ee);
}

// ---------------- launch 1: merged init (counters + ee + B frags) ----------------
__global__ void vq_init(const float* __restrict__ cb) {
    int id = blockIdx.x * blockDim.x + threadIdx.x;
    if (id == 0) { g_loss_sum = 0.0; g_n_pair = 0; g_n_full = 0; g_done = 0; }
    if (id < KC) {
        const float* er = cb + (size_t)id * EDIM;
        float ee = 0.f;
        #pragma unroll
        for (int k = 0; k < EDIM; ++k) ee = __fadd_rn(ee, __fmul_rn(er[k], er[k]));
        g_ee[id] = ee;
    }
    if (id < 16384) {
        int c = id >> 11, s = (id >> 9) & 3, l = (id >> 4) & 31, t = id & 15;
        int g = l >> 2, tig = l & 3;
        int n = c * 128 + t * 8 + g;
        int k0 = s * 16 + 2 * tig;
        const float* p = cb + (size_t)n * EDIM;
        float v0 = __fmul_rn(-2.f, p[k0]),     v1 = __fmul_rn(-2.f, p[k0 + 1]);
        float v2 = __fmul_rn(-2.f, p[k0 + 8]), v3 = __fmul_rn(-2.f, p[k0 + 9]);
        uint2 q;
        q.x = packbf(v0, v1);
        q.y = packbf(v2, v3);
        g_Bfrag[c * 2048 + s * 512 + l * 16 + (t ^ (l & 15))] = q;
    }
}

// ---------------- launch 2: screen (paired-key top-3, full 10-bit indices) ----------------
// smem: A staging [0,18432) overlaid by B buf0 [0,16384); B buf1 @18432
#define SMEM_SZ 34816

__device__ __forceinline__ void cp_chunk(uint32_t sb, uint32_t bufoff, int c, int tid) {
    uint32_t d0 = sb + bufoff;
    const char* src = (const char*)g_Bfrag + c * 16384;
    #pragma unroll
    for (int it = 0; it < 8; ++it) {
        int i = tid + it * 128;
        asm volatile("cp.async.cg.shared.global [%0], [%1], 16;"
                     :: "r"(d0 + i * 16), "l"(src + i * 16));
    }
}

__global__ __launch_bounds__(128, 5) void vq_screen(const float* __restrict__ x, int nrows) {
    extern __shared__ __align__(16) char sm[];
    uint32_t sb = smem_to_u32(sm);
    int tid = threadIdx.x, w = tid >> 5, l = tid & 31;
    int g = l >> 2, tig = l & 3;
    int m0 = blockIdx.x * 128;

    #pragma unroll
    for (int it = 0; it < 16; ++it) {
        int i = tid + it * 128;
        int row = i >> 4, q = i & 15;
        float4 v = make_float4(0.f, 0.f, 0.f, 0.f);
        if (m0 + row < nrows) v = ((const float4*)x)[(size_t)(m0 + row) * 16 + q];
        uint2 wv;
        wv.x = packbf(v.x, v.y); wv.y = packbf(v.z, v.w);
        *(uint2*)(sm + row * 144 + q * 8) = wv;
    }
    cp_chunk(sb, 18432, 0, tid);
    CP_COMMIT(); CP_WAIT0();
    __syncthreads();

    uint32_t AH[2][4][4];
    {
        int mat = l >> 3, r8 = l & 7;
        #pragma unroll
        for (int mt = 0; mt < 2; ++mt)
            #pragma unroll
            for (int s = 0; s < 4; ++s)
                ldmA(AH[mt][s], sb + (w * 32 + mt * 16 + (mat & 1) * 8 + r8) * 144
                                   + s * 32 + (mat >> 1) * 16);
    }
    __syncthreads();

    uint32_t m1[4] = {~0u, ~0u, ~0u, ~0u}, m2[4] = {~0u, ~0u, ~0u, ~0u},
             m3[4] = {~0u, ~0u, ~0u, ~0u};
    int slotx = l & 15;

    #pragma unroll 1
    for (int c = 0; c < 8; ++c) {
        uint32_t cur = ((c & 1) ^ 1) * 18432u;
        uint32_t nxt = (c & 1) * 18432u;
        if (c + 1 < 8) { cp_chunk(sb, nxt, c + 1, tid); CP_COMMIT(); }
        const uint2* bb = (const uint2*)(sm + cur);

        #pragma unroll 4
        for (int t = 0; t < 16; ++t) {
            float c0[4] = {0.25f, 0.25f, 0.25f, 0.25f};
            float c1[4] = {0.25f, 0.25f, 0.25f, 0.25f};
            int ts = t ^ slotx;
            #pragma unroll
            for (int s = 0; s < 4; ++s) {
                uint2 B = bb[s * 512 + l * 16 + ts];
                mma_bf16(c0, AH[0][s], B.x, B.y);
                mma_bf16(c1, AH[1][s], B.x, B.y);
            }
            uint32_t j0 = (uint32_t)(c * 128 + t * 8 + 2 * tig);
            #define UPD(r, vA, vB) do { \
                uint32_t kA = (__float_as_uint(vA) & 0xFFFFFC00u) | j0; \
                uint32_t kB = (__float_as_uint(vB) & 0xFFFFFC00u) | (j0 + 1u); \
                uint32_t _k = min(kA, kB); \
                uint32_t _t = max(m1[r], _k); m1[r] = min(m1[r], _k); \
                uint32_t _u = max(m2[r], _t); m2[r] = min(m2[r], _t); \
                m3[r] = min(m3[r], _u); \
            } while (0)
            UPD(0, c0[0], c0[1]);
            UPD(1, c0[2], c0[3]);
            UPD(2, c1[0], c1[1]);
            UPD(3, c1[2], c1[3]);
            #undef UPD
        }
        if (c + 1 < 8) CP_WAIT0();
        __syncthreads();
    }

    #pragma unroll
    for (int r = 0; r < 4; ++r) {
        uint32_t a1 = m1[r], a2 = m2[r], a3 = m3[r];
        #pragma unroll
        for (int off = 1; off <= 2; off <<= 1) {
            uint32_t o1 = __shfl_xor_sync(0xffffffffu, a1, off);
            uint32_t o2 = __shfl_xor_sync(0xffffffffu, a2, off);
            uint32_t o3 = __shfl_xor_sync(0xffffffffu, a3, off);
            uint32_t p1 = min(a1, o1), q1 = max(a1, o1);
            uint32_t p2 = min(a2, o2), q2 = max(a2, o2);
            uint32_t p3 = min(a3, o3);
            a1 = p1;
            a2 = min(q1, p2);
            a3 = min(max(q1, p2), min(q2, p3));
        }
        if (tig == 0) {
            int mt = r >> 1, slot = r & 1;
            int row = m0 + w * 32 + mt * 16 + g + slot * 8;
            if (row < nrows) {
                uint32_t i1 = a1 & 0x3FFu, i2 = a2 & 0x3FFu;
                g_codes[row] = (int)i1;
                float s1 = __uint_as_float(a1 & 0xFFFFFC00u);
                float s2 = __uint_as_float(a2 & 0xFFFFFC00u);
                float s3 = __uint_as_float(a3 & 0xFFFFFC00u);
                if (s2 - s1 < MARGIN) {
                    if (s3 - s1 >= MARGIN) {
                        int s = atomicAdd(&g_n_pair, 1);
                        g_pairs[s] = ((unsigned long long)row << 20)
                                   | ((unsigned long long)i1 << 10) | i2;
                    } else {
                        int s = atomicAdd(&g_n_full, 1);
                        g_full_rows[s] = row;
                        g_amb_key[s] = ~0ull;
                        g_seg_cnt[s] = 0;
                    }
                }
            }
        }
    }
}

// ---------------- launch 3: combined tail — pair rescore + full seg rescore + commit ----
#define PAIR_BLOCKS 64
__global__ __launch_bounds__(256) void vq_tail(const float* __restrict__ x,
                                               const float* __restrict__ cb) {
    if (blockIdx.x < PAIR_BLOCKS) {
        int np = g_n_pair;
        for (int s = blockIdx.x * blockDim.x + threadIdx.x; s < np;
             s += PAIR_BLOCKS * blockDim.x) {
            unsigned long long e = g_pairs[s];
            int row = (int)(e >> 20);
            int i1 = (int)((e >> 10) & 0x3FFu), i2 = (int)(e & 0x3FFu);
            float xv[EDIM];
            const float4* xr = (const float4*)(x + (size_t)row * EDIM);
            #pragma unroll
            for (int q = 0; q < 16; ++q) {
                float4 v = xr[q];
                xv[4*q] = v.x; xv[4*q+1] = v.y; xv[4*q+2] = v.z; xv[4*q+3] = v.w;
            }
            float xx = ref_xx(xv);
            float d1 = ref_dist(xv, cb + (size_t)i1 * EDIM, xx, g_ee[i1]);
            float d2 = ref_dist(xv, cb + (size_t)i2 * EDIM, xx, g_ee[i2]);
            int win = i1;
            if (d2 < d1 || (d2 == d1 && i2 < i1)) win = i2;
            g_codes[row] = win;
        }
        return;
    }
    // ---- full rescore (rare), smem-tiled segmented; 8th segment commits ----
    __shared__ float s_e[128 * EDIM];
    int na = g_n_full;
    int nwork = ((na + 255) >> 8) * 8;
    int nblk = gridDim.x - PAIR_BLOCKS;
    #pragma unroll 1
    for (int wk = blockIdx.x - PAIR_BLOCKS; wk < nwork; wk += nblk) {
        int seg = wk & 7, base = (wk >> 3) << 8;
        __syncthreads();
        const float4* g4 = (const float4*)(cb + (size_t)seg * 128 * EDIM);
        for (int i = threadIdx.x; i < 2048; i += 256) ((float4*)s_e)[i] = g4[i];
        __syncthreads();
        int s = base + threadIdx.x;
        if (s < na) {
            int row = g_full_rows[s];
            const float* xr = x + (size_t)row * EDIM;
            float xv[EDIM];
            #pragma unroll
            for (int k = 0; k < EDIM; ++k) xv[k] = xr[k];
            float xx = ref_xx(xv);
            float bd = 3.4e38f; int bi = 0x7fffffff;
            #pragma unroll 1
            for (int jj = 0; jj < 128; jj += 4) {
                const float4* e = (const float4*)(s_e + jj * EDIM);
                float a0 = 0.f, a1 = 0.f, a2 = 0.f, a3 = 0.f;
                #pragma unroll
                for (int q = 0; q < 16; ++q) {
                    float4 v0 = e[q], v1 = e[16 + q], v2 = e[32 + q], v3 = e[48 + q];
                    a0 = __fmaf_rn(xv[4*q],   v0.x, a0); a0 = __fmaf_rn(xv[4*q+1], v0.y, a0);
                    a0 = __fmaf_rn(xv[4*q+2], v0.z, a0); a0 = __fmaf_rn(xv[4*q+3], v0.w, a0);
                    a1 = __fmaf_rn(xv[4*q],   v1.x, a1); a1 = __fmaf_rn(xv[4*q+1], v1.y, a1);
                    a1 = __fmaf_rn(xv[4*q+2], v1.z, a1); a1 = __fmaf_rn(xv[4*q+3], v1.w, a1);
                    a2 = __fmaf_rn(xv[4*q],   v2.x, a2); a2 = __fmaf_rn(xv[4*q+1], v2.y, a2);
                    a2 = __fmaf_rn(xv[4*q+2], v2.z, a2); a2 = __fmaf_rn(xv[4*q+3], v2.w, a2);
                    a3 = __fmaf_rn(xv[4*q],   v3.x, a3); a3 = __fmaf_rn(xv[4*q+1], v3.y, a3);
                    a3 = __fmaf_rn(xv[4*q+2], v3.z, a3); a3 = __fmaf_rn(xv[4*q+3], v3.w, a3);
                }
                int j0 = seg * 128 + jj;
                float d0 = __fadd_rn(__fadd_rn(xx, __fmul_rn(-2.f, a0)), g_ee[j0]);
                float d1 = __fadd_rn(__fadd_rn(xx, __fmul_rn(-2.f, a1)), g_ee[j0 + 1]);
                float d2 = __fadd_rn(__fadd_rn(xx, __fmul_rn(-2.f, a2)), g_ee[j0 + 2]);
                float d3 = __fadd_rn(__fadd_rn(xx, __fmul_rn(-2.f, a3)), g_ee[j0 + 3]);
                if (d0 < bd) { bd = d0; bi = j0; }
                if (d1 < bd) { bd = d1; bi = j0 + 1; }
                if (d2 < bd) { bd = d2; bi = j0 + 2; }
                if (d3 < bd) { bd = d3; bi = j0 + 3; }
            }
            unsigned long long key =
                ((unsigned long long)__float_as_uint(bd) << 32) | (unsigned)bi;
            atomicMin(&g_amb_key[s], key);
            __threadfence();
            int done = atomicAdd(&g_seg_cnt[s], 1);
            if (done == 7) {
                unsigned long long fin = atomicAdd(&g_amb_key[s], 0ull);
                g_codes[row] = (int)(unsigned)(fin & 0xffffffffull);
            }
        }
    }
}

// ---------------- launch 4: straight_through + loss + codes (8 chunks/thread) ----------
__global__ __launch_bounds__(256) void vq_st_loss_kernel(
    const float* __restrict__ x, const float* __restrict__ cb,
    float* __restrict__ out, int nrows, long long out_size)
{
    __shared__ double sred[8];
    const unsigned long long SGN = 0x8000000080000000ull;
    int q = nrows * 2;                         // 8 float4-chunks per thread
    int idx = blockIdx.x * 256 + threadIdx.x;
    long long coff = (long long)nrows * EDIM;
    unsigned long long lacc = 0ull;
    if (idx < q) {
        int i4[8]; int code[8];
        #pragma unroll
        for (int t = 0; t < 8; ++t) { i4[t] = idx + t * q; code[t] = g_codes[i4[t] >> 4]; }
        ulonglong2 xv[8], qv[8];
        #pragma unroll
        for (int t = 0; t < 8; ++t) {
            xv[t] = ((const ulonglong2*)x)[i4[t]];
            qv[t] = ((const ulonglong2*)cb)[(size_t)code[t] * 16 + (i4[t] & 15)];
        }
        #pragma unroll
        for (int t = 0; t < 8; ++t) {
            unsigned long long d0 = addf2(qv[t].x, xv[t].x ^ SGN);   // q - x (exact, lanewise)
            unsigned long long d1 = addf2(qv[t].y, xv[t].y ^ SGN);
            ulonglong2 st;
            st.x = addf2(xv[t].x, d0);                               // x + (q - x)
            st.y = addf2(xv[t].y, d1);
            ((ulonglong2*)out)[i4[t]] = st;
            lacc = fmaf2(d0, d0, lacc);
            lacc = fmaf2(d1, d1, lacc);
            if ((i4[t] & 15) == 0) out[coff + (i4[t] >> 4)] = (float)code[t];
        }
    }
    float llo = __uint_as_float((uint32_t)(lacc & 0xffffffffull));
    float lhi = __uint_as_float((uint32_t)(lacc >> 32));
    double ls = (double)llo + (double)lhi;
    #pragma unroll
    for (int off = 16; off; off >>= 1) ls += __shfl_down_sync(0xffffffffu, ls, off);
    if ((threadIdx.x & 31) == 0) sred[threadIdx.x >> 5] = ls;
    __syncthreads();
    if (threadIdx.x == 0) {
        double tot = sred[0];
        #pragma unroll
        for (int i = 1; i < 8; ++i) tot += sred[i];
        atomicAdd(&g_loss_sum, tot);                 // ONE global atomic per block
        __threadfence();
        int done = atomicAdd(&g_done, 1);
        if (done == (int)gridDim.x - 1) {
            double total = atomicAdd(&g_loss_sum, 0.0);
            double mean = total / (double)((long long)nrows * EDIM);
            float mf = (float)mean;
            if (coff + nrows < out_size)
                out[coff + nrows] = __fadd_rn(mf, __fmul_rn(0.25f, mf));
        }
    }
}

// ---------------- launch ----------------
extern "C" void kernel_launch(void* const* d_in, const int* in_sizes, int n_in,
                              void* d_out, int out_size)
{
    const float* x  = (const float*)d_in[0];
    const float* cb = (const float*)d_in[1];
    int nx = in_sizes[0], nc = in_sizes[1];
    if (nx < nc) {
        const float* t = x; x = cb; cb = t;
        int ti = nx; nx = nc; nc = ti;
    }
    int nrows = nx / EDIM;
    float* out = (float*)d_out;

    vq_init<<<64, 256>>>(cb);
    vq_screen<<<(nrows + 127) / 128, 128, SMEM_SZ>>>(x, nrows);
    vq_tail<<<PAIR_BLOCKS + 192, 256>>>(x, cb);
    vq_st_loss_kernel<<<(nrows * 2 + 255) / 256, 256>>>(x, cb, out, nrows,
                                                        (long long)out_size);
}

// round 16
// speedup vs baseline: 1.0371x; 1.0371x over previous
#include <cuda_runtime.h>
#include <cstdint>

#define EDIM  64
#define KC    1024
#define NMAX  131072
#define MARGIN 3.2e-4f

// ---------------- device scratch ----------------
__device__ __align__(16) uint2 g_Bfrag[16384];  // [c][s][lane][slot16] bf16(-2cb) frags
__device__ float  g_ee[KC];
__device__ int    g_codes[NMAX];
__device__ unsigned long long g_pairs[NMAX];    // (row<<20)|(i1<<10)|i2
__device__ int    g_full_rows[NMAX];
__device__ unsigned long long g_amb_key[NMAX];
__device__ int    g_seg_cnt[NMAX];
__device__ int    g_n_pair, g_n_full, g_done;
__device__ double g_loss_sum;

// ---------------- helpers ----------------
__device__ __forceinline__ uint32_t smem_to_u32(const void* p) {
    uint32_t a;
    asm("{ .reg .u64 t; cvta.to.shared.u64 t, %1; cvt.u32.u64 %0, t; }" : "=r"(a) : "l"(p));
    return a;
}
__device__ __forceinline__ uint32_t packbf(float lo, float hi) {
    uint32_t r;
    asm("cvt.rn.bf16x2.f32 %0, %1, %2;" : "=r"(r) : "f"(hi), "f"(lo));
    return r;
}
__device__ __forceinline__ void mma_bf16(float* c, const uint32_t* a, uint32_t b0, uint32_t b1) {
    asm volatile("mma.sync.aligned.m16n8k16.row.col.f32.bf16.bf16.f32 "
                 "{%0,%1,%2,%3},{%4,%5,%6,%7},{%8,%9},{%0,%1,%2,%3};"
                 : "+f"(c[0]), "+f"(c[1]), "+f"(c[2]), "+f"(c[3])
                 : "r"(a[0]), "r"(a[1]), "r"(a[2]), "r"(a[3]), "r"(b0), "r"(b1));
}
__device__ __forceinline__ void ldmA(uint32_t* r, uint32_t addr) {
    asm volatile("ldmatrix.sync.aligned.m8n8.x4.shared.b16 {%0,%1,%2,%3}, [%4];"
                 : "=r"(r[0]), "=r"(r[1]), "=r"(r[2]), "=r"(r[3]) : "r"(addr));
}
__device__ __forceinline__ unsigned long long addf2(unsigned long long a, unsigned long long b) {
    unsigned long long r;
    asm("add.rn.f32x2 %0, %1, %2;" : "=l"(r) : "l"(a), "l"(b));
    return r;
}
__device__ __forceinline__ unsigned long long fmaf2(unsigned long long a, unsigned long long b,
                                                    unsigned long long c) {
    unsigned long long r;
    asm("fma.rn.f32x2 %0, %1, %2, %3;" : "=l"(r) : "l"(a), "l"(b), "l"(c));
    return r;
}
#define CP_COMMIT() asm volatile("cp.async.commit_group;" ::: "memory")
#define CP_WAIT0()  asm volatile("cp.async.wait_group 0;" ::: "memory")

__device__ __forceinline__ float ref_xx(const float* xv) {
    float xx = 0.f;
    #pragma unroll
    for (int k = 0; k < EDIM; ++k) xx = __fadd_rn(xx, __fmul_rn(xv[k], xv[k]));
    return xx;
}
__device__ __forceinline__ float ref_dist(const float* xv, const float* e, float xx, float ee) {
    float a = 0.f;
    #pragma unroll
    for (int k = 0; k < EDIM; ++k) a = __fmaf_rn(xv[k], e[k], a);
    return __fadd_rn(__fadd_rn(xx, __fmul_rn(-2.f, a)), ee);
}

// ---------------- launch 1: merged init (counters + ee + B frags) ----------------
__global__ void vq_init(const float* __restrict__ cb) {
    int id = blockIdx.x * blockDim.x + threadIdx.x;
    if (id == 0) { g_loss_sum = 0.0; g_n_pair = 0; g_n_full = 0; g_done = 0; }
    if (id < KC) {
        const float* er = cb + (size_t)id * EDIM;
        float ee = 0.f;
        #pragma unroll
        for (int k = 0; k < EDIM; ++k) ee = __fadd_rn(ee, __fmul_rn(er[k], er[k]));
        g_ee[id] = ee;
    }
    if (id < 16384) {
        int c = id >> 11, s = (id >> 9) & 3, l = (id >> 4) & 31, t = id & 15;
        int g = l >> 2, tig = l & 3;
        int n = c * 128 + t * 8 + g;
        int k0 = s * 16 + 2 * tig;
        const float* p = cb + (size_t)n * EDIM;
        float v0 = __fmul_rn(-2.f, p[k0]),     v1 = __fmul_rn(-2.f, p[k0 + 1]);
        float v2 = __fmul_rn(-2.f, p[k0 + 8]), v3 = __fmul_rn(-2.f, p[k0 + 9]);
        uint2 q;
        q.x = packbf(v0, v1);
        q.y = packbf(v2, v3);
        g_Bfrag[c * 2048 + s * 512 + l * 16 + (t ^ (l & 15))] = q;
    }
}

// ---------------- launch 2: screen (paired-key top-3, full 10-bit indices) ----------------
// smem: A staging [0,18432) overlaid by B buf0 [0,16384); B buf1 @18432
#define SMEM_SZ 34816

__device__ __forceinline__ void cp_chunk(uint32_t sb, uint32_t bufoff, int c, int tid) {
    uint32_t d0 = sb + bufoff;
    const char* src = (const char*)g_Bfrag + c * 16384;
    #pragma unroll
    for (int it = 0; it < 8; ++it) {
        int i = tid + it * 128;
        asm volatile("cp.async.cg.shared.global [%0], [%1], 16;"
                     :: "r"(d0 + i * 16), "l"(src + i * 16));
    }
}

__global__ __launch_bounds__(128, 4) void vq_screen(const float* __restrict__ x, int nrows) {
    extern __shared__ __align__(16) char sm[];
    uint32_t sb = smem_to_u32(sm);
    int tid = threadIdx.x, w = tid >> 5, l = tid & 31;
    int g = l >> 2, tig = l & 3;
    int m0 = blockIdx.x * 128;

    #pragma unroll
    for (int it = 0; it < 16; ++it) {
        int i = tid + it * 128;
        int row = i >> 4, q = i & 15;
        float4 v = make_float4(0.f, 0.f, 0.f, 0.f);
        if (m0 + row < nrows) v = ((const float4*)x)[(size_t)(m0 + row) * 16 + q];
        uint2 wv;
        wv.x = packbf(v.x, v.y); wv.y = packbf(v.z, v.w);
        *(uint2*)(sm + row * 144 + q * 8) = wv;
    }
    cp_chunk(sb, 18432, 0, tid);
    CP_COMMIT(); CP_WAIT0();
    __syncthreads();

    uint32_t AH[2][4][4];
    {
        int mat = l >> 3, r8 = l & 7;
        #pragma unroll
        for (int mt = 0; mt < 2; ++mt)
            #pragma unroll
            for (int s = 0; s < 4; ++s)
                ldmA(AH[mt][s], sb + (w * 32 + mt * 16 + (mat & 1) * 8 + r8) * 144
                                   + s * 32 + (mat >> 1) * 16);
    }
    __syncthreads();

    uint32_t m1[4] = {~0u, ~0u, ~0u, ~0u}, m2[4] = {~0u, ~0u, ~0u, ~0u},
             m3[4] = {~0u, ~0u, ~0u, ~0u};
    int slotx = l & 15;

    #pragma unroll 1
    for (int c = 0; c < 8; ++c) {
        uint32_t cur = ((c & 1) ^ 1) * 18432u;
        uint32_t nxt = (c & 1) * 18432u;
        if (c + 1 < 8) { cp_chunk(sb, nxt, c + 1, tid); CP_COMMIT(); }
        const uint2* bb = (const uint2*)(sm + cur);

        #pragma unroll 4
        for (int t = 0; t < 16; ++t) {
            float c0[4] = {0.25f, 0.25f, 0.25f, 0.25f};
            float c1[4] = {0.25f, 0.25f, 0.25f, 0.25f};
            int ts = t ^ slotx;
            #pragma unroll
            for (int s = 0; s < 4; ++s) {
                uint2 B = bb[s * 512 + l * 16 + ts];
                mma_bf16(c0, AH[0][s], B.x, B.y);
                mma_bf16(c1, AH[1][s], B.x, B.y);
            }
            uint32_t j0 = (uint32_t)(c * 128 + t * 8 + 2 * tig);
            #define UPD(r, vA, vB) do { \
                uint32_t kA = (__float_as_uint(vA) & 0xFFFFFC00u) | j0; \
                uint32_t kB = (__float_as_uint(vB) & 0xFFFFFC00u) | (j0 + 1u); \
                uint32_t _k = min(kA, kB); \
                uint32_t _t = max(m1[r], _k); m1[r] = min(m1[r], _k); \
                uint32_t _u = max(m2[r], _t); m2[r] = min(m2[r], _t); \
                m3[r] = min(m3[r], _u); \
            } while (0)
            UPD(0, c0[0], c0[1]);
            UPD(1, c0[2], c0[3]);
            UPD(2, c1[0], c1[1]);
            UPD(3, c1[2], c1[3]);
            #undef UPD
        }
        if (c + 1 < 8) CP_WAIT0();
        __syncthreads();
    }

    #pragma unroll
    for (int r = 0; r < 4; ++r) {
        uint32_t a1 = m1[r], a2 = m2[r], a3 = m3[r];
        #pragma unroll
        for (int off = 1; off <= 2; off <<= 1) {
            uint32_t o1 = __shfl_xor_sync(0xffffffffu, a1, off);
            uint32_t o2 = __shfl_xor_sync(0xffffffffu, a2, off);
            uint32_t o3 = __shfl_xor_sync(0xffffffffu, a3, off);
            uint32_t p1 = min(a1, o1), q1 = max(a1, o1);
            uint32_t p2 = min(a2, o2), q2 = max(a2, o2);
            uint32_t p3 = min(a3, o3);
            a1 = p1;
            a2 = min(q1, p2);
            a3 = min(max(q1, p2), min(q2, p3));
        }
        if (tig == 0) {
            int mt = r >> 1, slot = r & 1;
            int row = m0 + w * 32 + mt * 16 + g + slot * 8;
            if (row < nrows) {
                uint32_t i1 = a1 & 0x3FFu, i2 = a2 & 0x3FFu;
                g_codes[row] = (int)i1;
                float s1 = __uint_as_float(a1 & 0xFFFFFC00u);
                float s2 = __uint_as_float(a2 & 0xFFFFFC00u);
                float s3 = __uint_as_float(a3 & 0xFFFFFC00u);
                if (s2 - s1 < MARGIN) {
                    if (s3 - s1 >= MARGIN) {
                        int s = atomicAdd(&g_n_pair, 1);
                        g_pairs[s] = ((unsigned long long)row << 20)
                                   | ((unsigned long long)i1 << 10) | i2;
                    } else {
                        int s = atomicAdd(&g_n_full, 1);
                        g_full_rows[s] = row;
                        g_amb_key[s] = ~0ull;
                        g_seg_cnt[s] = 0;
                    }
                }
            }
        }
    }
}

// ---------------- launch 3: combined tail — pair rescore + full seg rescore + commit ----
#define PAIR_BLOCKS 64
__global__ __launch_bounds__(256) void vq_tail(const float* __restrict__ x,
                                               const float* __restrict__ cb) {
    if (blockIdx.x < PAIR_BLOCKS) {
        int np = g_n_pair;
        for (int s = blockIdx.x * blockDim.x + threadIdx.x; s < np;
             s += PAIR_BLOCKS * blockDim.x) {
            unsigned long long e = g_pairs[s];
            int row = (int)(e >> 20);
            int i1 = (int)((e >> 10) & 0x3FFu), i2 = (int)(e & 0x3FFu);
            float xv[EDIM];
            const float4* xr = (const float4*)(x + (size_t)row * EDIM);
            #pragma unroll
            for (int q = 0; q < 16; ++q) {
                float4 v = xr[q];
                xv[4*q] = v.x; xv[4*q+1] = v.y; xv[4*q+2] = v.z; xv[4*q+3] = v.w;
            }
            float xx = ref_xx(xv);
            float d1 = ref_dist(xv, cb + (size_t)i1 * EDIM, xx, g_ee[i1]);
            float d2 = ref_dist(xv, cb + (size_t)i2 * EDIM, xx, g_ee[i2]);
            int win = i1;
            if (d2 < d1 || (d2 == d1 && i2 < i1)) win = i2;
            g_codes[row] = win;
        }
        return;
    }
    // ---- full rescore (rare), smem-tiled segmented; 8th segment commits ----
    __shared__ float s_e[128 * EDIM];
    int na = g_n_full;
    int nwork = ((na + 255) >> 8) * 8;
    int nblk = gridDim.x - PAIR_BLOCKS;
    #pragma unroll 1
    for (int wk = blockIdx.x - PAIR_BLOCKS; wk < nwork; wk += nblk) {
        int seg = wk & 7, base = (wk >> 3) << 8;
        __syncthreads();
        const float4* g4 = (const float4*)(cb + (size_t)seg * 128 * EDIM);
        for (int i = threadIdx.x; i < 2048; i += 256) ((float4*)s_e)[i] = g4[i];
        __syncthreads();
        int s = base + threadIdx.x;
        if (s < na) {
            int row = g_full_rows[s];
            const float* xr = x + (size_t)row * EDIM;
            float xv[EDIM];
            #pragma unroll
            for (int k = 0; k < EDIM; ++k) xv[k] = xr[k];
            float xx = ref_xx(xv);
            float bd = 3.4e38f; int bi = 0x7fffffff;
            #pragma unroll 1
            for (int jj = 0; jj < 128; jj += 4) {
                const float4* e = (const float4*)(s_e + jj * EDIM);
                float a0 = 0.f, a1 = 0.f, a2 = 0.f, a3 = 0.f;
                #pragma unroll
                for (int q = 0; q < 16; ++q) {
                    float4 v0 = e[q], v1 = e[16 + q], v2 = e[32 + q], v3 = e[48 + q];
                    a0 = __fmaf_rn(xv[4*q],   v0.x, a0); a0 = __fmaf_rn(xv[4*q+1], v0.y, a0);
                    a0 = __fmaf_rn(xv[4*q+2], v0.z, a0); a0 = __fmaf_rn(xv[4*q+3], v0.w, a0);
                    a1 = __fmaf_rn(xv[4*q],   v1.x, a1); a1 = __fmaf_rn(xv[4*q+1], v1.y, a1);
                    a1 = __fmaf_rn(xv[4*q+2], v1.z, a1); a1 = __fmaf_rn(xv[4*q+3], v1.w, a1);
                    a2 = __fmaf_rn(xv[4*q],   v2.x, a2); a2 = __fmaf_rn(xv[4*q+1], v2.y, a2);
                    a2 = __fmaf_rn(xv[4*q+2], v2.z, a2); a2 = __fmaf_rn(xv[4*q+3], v2.w, a2);
                    a3 = __fmaf_rn(xv[4*q],   v3.x, a3); a3 = __fmaf_rn(xv[4*q+1], v3.y, a3);
                    a3 = __fmaf_rn(xv[4*q+2], v3.z, a3); a3 = __fmaf_rn(xv[4*q+3], v3.w, a3);
                }
                int j0 = seg * 128 + jj;
                float d0 = __fadd_rn(__fadd_rn(xx, __fmul_rn(-2.f, a0)), g_ee[j0]);
                float d1 = __fadd_rn(__fadd_rn(xx, __fmul_rn(-2.f, a1)), g_ee[j0 + 1]);
                float d2 = __fadd_rn(__fadd_rn(xx, __fmul_rn(-2.f, a2)), g_ee[j0 + 2]);
                float d3 = __fadd_rn(__fadd_rn(xx, __fmul_rn(-2.f, a3)), g_ee[j0 + 3]);
                if (d0 < bd) { bd = d0; bi = j0; }
                if (d1 < bd) { bd = d1; bi = j0 + 1; }
                if (d2 < bd) { bd = d2; bi = j0 + 2; }
                if (d3 < bd) { bd = d3; bi = j0 + 3; }
            }
            unsigned long long key =
                ((unsigned long long)__float_as_uint(bd) << 32) | (unsigned)bi;
            atomicMin(&g_amb_key[s], key);
            __threadfence();
            int done = atomicAdd(&g_seg_cnt[s], 1);
            if (done == 7) {
                unsigned long long fin = atomicAdd(&g_amb_key[s], 0ull);
                g_codes[row] = (int)(unsigned)(fin & 0xffffffffull);
            }
        }
    }
}

// ---------------- launch 4: straight_through + loss + codes (8 chunks/thread) ----------
__global__ __launch_bounds__(256) void vq_st_loss_kernel(
    const float* __restrict__ x, const float* __restrict__ cb,
    float* __restrict__ out, int nrows, long long out_size)
{
    __shared__ double sred[8];
    const unsigned long long SGN = 0x8000000080000000ull;
    int q = nrows * 2;                         // 8 float4-chunks per thread
    int idx = blockIdx.x * 256 + threadIdx.x;
    long long coff = (long long)nrows * EDIM;
    unsigned long long lacc = 0ull;
    if (idx < q) {
        int i4[8]; int code[8];
        #pragma unroll
        for (int t = 0; t < 8; ++t) { i4[t] = idx + t * q; code[t] = g_codes[i4[t] >> 4]; }
        ulonglong2 xv[8], qv[8];
        #pragma unroll
        for (int t = 0; t < 8; ++t) {
            xv[t] = ((const ulonglong2*)x)[i4[t]];
            qv[t] = ((const ulonglong2*)cb)[(size_t)code[t] * 16 + (i4[t] & 15)];
        }
        #pragma unroll
        for (int t = 0; t < 8; ++t) {
            unsigned long long d0 = addf2(qv[t].x, xv[t].x ^ SGN);   // q - x (exact, lanewise)
            unsigned long long d1 = addf2(qv[t].y, xv[t].y ^ SGN);
            ulonglong2 st;
            st.x = addf2(xv[t].x, d0);                               // x + (q - x)
            st.y = addf2(xv[t].y, d1);
            ((ulonglong2*)out)[i4[t]] = st;
            lacc = fmaf2(d0, d0, lacc);
            lacc = fmaf2(d1, d1, lacc);
            if ((i4[t] & 15) == 0) out[coff + (i4[t] >> 4)] = (float)code[t];
        }
    }
    float llo = __uint_as_float((uint32_t)(lacc & 0xffffffffull));
    float lhi = __uint_as_float((uint32_t)(lacc >> 32));
    double ls = (double)llo + (double)lhi;
    #pragma unroll
    for (int off = 16; off; off >>= 1) ls += __shfl_down_sync(0xffffffffu, ls, off);
    if ((threadIdx.x & 31) == 0) sred[threadIdx.x >> 5] = ls;
    __syncthreads();
    if (threadIdx.x == 0) {
        double tot = sred[0];
        #pragma unroll
        for (int i = 1; i < 8; ++i) tot += sred[i];
        atomicAdd(&g_loss_sum, tot);                 // ONE global atomic per block
        __threadfence();
        int done = atomicAdd(&g_done, 1);
        if (done == (int)gridDim.x - 1) {
            double total = atomicAdd(&g_loss_sum, 0.0);
            double mean = total / (double)((long long)nrows * EDIM);
            float mf = (float)mean;
            if (coff + nrows < out_size)
                out[coff + nrows] = __fadd_rn(mf, __fmul_rn(0.25f, mf));
        }
    }
}

// ---------------- launch ----------------
extern "C" void kernel_launch(void* const* d_in, const int* in_sizes, int n_in,
                              void* d_out, int out_size)
{
    const float* x  = (const float*)d_in[0];
    const float* cb = (const float*)d_in[1];
    int nx = in_sizes[0], nc = in_sizes[1];
    if (nx < nc) {
        const float* t = x; x = cb; cb = t;
        int ti = nx; nx = nc; nc = ti;
    }
    int nrows = nx / EDIM;
    float* out = (float*)d_out;

    vq_init<<<64, 256>>>(cb);
    vq_screen<<<(nrows + 127) / 128, 128, SMEM_SZ>>>(x, nrows);
    vq_tail<<<PAIR_BLOCKS + 192, 256>>>(x, cb);
    vq_st_loss_kernel<<<(nrows * 2 + 255) / 256, 256>>>(x, cb, out, nrows,
                                                        (long long)out_size);
}